// round 11
// baseline (speedup 1.0000x reference)
#include <cuda_runtime.h>

// ConstrainNet residual:
//   out[0:64]            = V[0,:64] - x0
//   out[t*64 : t*64+64]  = [A B] @ V[t-1] - V[t,:64]   for t = 1..T-1
// Shapes: A (64,64), B (64,32), x0 (64), net_input = V (T=128, 96), out (T*64,)
//
// 32 CTAs x 128 threads, thread = (s, kh). Each thread stages its 48-float
// AB row segment ONCE (12 LDG.128) and reuses it for FOUR timesteps
// (t0..t0+3): four independent 48-FMA/4-acc chains (ILP 4), one shfl_xor(1)
// per timestep to combine k-halves. No smem, no barriers. Gating loads
// (V[t][s], x0) issue first.

constexpr int NS = 64;
constexpr int NA = 96;
constexpr int T  = 128;
constexpr int BT = 4;
constexpr int THREADS = 128;   // 64 rows * 2 k-halves

__global__ __launch_bounds__(THREADS, 1)
void constrainnet_kernel(const float* __restrict__ A,
                         const float* __restrict__ B,
                         const float* __restrict__ x0,
                         const float* __restrict__ V,
                         float* __restrict__ out) {
    const unsigned tid = threadIdx.x;
    const unsigned s   = tid >> 1;     // output row
    const unsigned kh  = tid & 1;      // k-half
    const int t0 = (int)(blockIdx.x * BT);

    // Loads gating the final subtracts: issue immediately.
    float vts[BT];
    #pragma unroll
    for (int g = 0; g < BT; ++g)
        vts[g] = __ldg(&V[(t0 + g) * NA + s]);
    const float x0s = (t0 == 0) ? __ldg(&x0[s]) : 0.0f;

    // AB row s, k-segment [kh*48, kh*48+48):
    //   kh=0: A[s][0:16) | A[s][16:48)
    //   kh=1: A[s][48:64) | B[s][0:32)
    const float4* X4 = reinterpret_cast<const float4*>(A + s * 64 + kh * 48);
    const float4* Y4 = kh ? reinterpret_cast<const float4*>(B + s * 32)
                          : reinterpret_cast<const float4*>(A + s * 64 + 16);

    // V row pointers for the BT dot products (row t0-1 .. t0+BT-2), clamped.
    const float4* Vp[BT];
    #pragma unroll
    for (int g = 0; g < BT; ++g) {
        int tp = t0 + g - 1;
        if (tp < 0) tp = 0;            // t==0 result overridden below
        Vp[g] = reinterpret_cast<const float4*>(V + tp * NA + kh * 48);
    }

    // Stage AB segment once (12 independent 128-bit loads).
    float4 ab[12];
    #pragma unroll
    for (int j = 0; j < 4; ++j) ab[j] = X4[j];
    #pragma unroll
    for (int j = 0; j < 8; ++j) ab[4 + j] = Y4[j];

    // Four independent 48-FMA dot products sharing the staged AB registers.
    float acc[BT][4];
    #pragma unroll
    for (int g = 0; g < BT; ++g)
        acc[g][0] = acc[g][1] = acc[g][2] = acc[g][3] = 0.0f;

    #pragma unroll
    for (int j = 0; j < 12; ++j) {
        const float4 a = ab[j];
        #pragma unroll
        for (int g = 0; g < BT; ++g) {
            float4 v = Vp[g][j];
            acc[g][0] = fmaf(a.x, v.x, acc[g][0]);
            acc[g][1] = fmaf(a.y, v.y, acc[g][1]);
            acc[g][2] = fmaf(a.z, v.z, acc[g][2]);
            acc[g][3] = fmaf(a.w, v.w, acc[g][3]);
        }
    }

    float r[BT];
    #pragma unroll
    for (int g = 0; g < BT; ++g) {
        float dot = (acc[g][0] + acc[g][1]) + (acc[g][2] + acc[g][3]);
        dot += __shfl_xor_sync(0xFFFFFFFFu, dot, 1);
        r[g] = dot - vts[g];
    }
    if (t0 == 0) r[0] = vts[0] - x0s;

    if (kh == 0) {
        #pragma unroll
        for (int g = 0; g < BT; ++g)
            out[(t0 + g) * NS + s] = r[g];
    }
}

extern "C" void kernel_launch(void* const* d_in, const int* in_sizes, int n_in,
                              void* d_out, int out_size) {
    const float* A  = (const float*)d_in[0];
    const float* B  = (const float*)d_in[1];
    const float* x0 = (const float*)d_in[2];
    const float* V  = (const float*)d_in[3];
    float* out = (float*)d_out;

    constrainnet_kernel<<<T / BT, THREADS>>>(A, B, x0, V, out);
}